// round 15
// baseline (speedup 1.0000x reference)
#include <cuda_runtime.h>
#include <cuda_fp16.h>
#include <cstdint>

// ---------------------------------------------------------------------------
// Problem constants
// ---------------------------------------------------------------------------
namespace {
constexpr int B  = 8;
constexpr int T  = 2048;
constexpr int D  = 1024;
constexpr int H  = 16;
constexpr int NL = 4;
constexpr int DK = 64;           // D / H
constexpr int M  = B * T;        // 16384 rows
constexpr int F  = 4 * D;        // 4096 ffn hidden
constexpr int NSPL = 8;          // kv T-splits
constexpr size_t DD   = (size_t)D * D;
constexpr size_t DF   = (size_t)D * F;
constexpr size_t WBLK = 4 * DD + 2 * DF;   // weight block per layer
}

// ---------------------------------------------------------------------------
// Scratch (static device memory — no allocations allowed)
// ---------------------------------------------------------------------------
__device__ __half g_hh[(size_t)M * D];     // LN out (fp16)
__device__ __half g_oh[(size_t)M * D];     // attn out (fp16)
__device__ __half g_fh[(size_t)M * F];     // relu(ffn) (fp16)
__device__ __half g_q[(size_t)M * D];
__device__ __half g_k[(size_t)M * D];
__device__ __half g_v[(size_t)M * D];
__device__ float g_kvp [B * H * NSPL * DK * DK];   // kv partials
__device__ float g_ksp [B * H * NSPL * DK];        // ksum partials
__device__ float g_kv  [B * H * DK * DK];
__device__ float g_ksum[B * H * DK];
__device__ __half g_wh[(size_t)NL * WBLK]; // transposed weights [N][K] fp16

// ---------------------------------------------------------------------------
// Helpers
// ---------------------------------------------------------------------------
__device__ __forceinline__ uint32_t smem_u32(const void* p) {
    uint32_t a;
    asm("{ .reg .u64 t; cvta.to.shared.u64 t, %1; cvt.u32.u64 %0, t; }" : "=r"(a) : "l"(p));
    return a;
}
__device__ __forceinline__ void ldmx4(uint32_t* r, uint32_t addr) {
    asm volatile("ldmatrix.sync.aligned.m8n8.x4.shared.b16 {%0,%1,%2,%3}, [%4];"
                 : "=r"(r[0]), "=r"(r[1]), "=r"(r[2]), "=r"(r[3]) : "r"(addr));
}
// fp16-accumulate MMA: D(f16x2 x2) += A x B
__device__ __forceinline__ void mma16816h(uint32_t* d, const uint32_t* a, const uint32_t* b) {
    asm volatile(
        "mma.sync.aligned.m16n8k16.row.col.f16.f16.f16.f16 "
        "{%0,%1}, {%2,%3,%4,%5}, {%6,%7}, {%0,%1};"
        : "+r"(d[0]), "+r"(d[1])
        : "r"(a[0]), "r"(a[1]), "r"(a[2]), "r"(a[3]), "r"(b[0]), "r"(b[1]));
}
#define CP_ASYNC16(dst, src) \
    asm volatile("cp.async.cg.shared.global [%0], [%1], 16;" :: "r"(dst), "l"(src))
#define CP_COMMIT() asm volatile("cp.async.commit_group;" ::: "memory")
#define CP_WAIT1()  asm volatile("cp.async.wait_group 1;" ::: "memory")
#define CP_WAIT0()  asm volatile("cp.async.wait_group 0;" ::: "memory")

__device__ __forceinline__ void h8_to_f(const uint4& u, float* f) {
    const __half2* h2 = reinterpret_cast<const __half2*>(&u);
#pragma unroll
    for (int i = 0; i < 4; ++i) {
        float2 t = __half22float2(h2[i]);
        f[i * 2] = t.x; f[i * 2 + 1] = t.y;
    }
}

// ---------------------------------------------------------------------------
// mma.sync fp16 GEMM (fp16 accumulate, 4 CTAs/SM target):
//   out = op( A[M,K] @ B[N,K]^T + bias )
// CTA 128x128, BK=32, 2-stage cp.async pipeline, 8 warps (4x2), 32 warps/SM
// acc[2][8][2]=32 regs; narrow operand live range (8 A + 4 B) -> regs <= 64
// MODE 0: plain -> fp16   1: relu -> fp16   2: residual add -> fp32
// MODE 3: elu+1 -> fp16   4: fused qkv (col block selects q/k/v + activation)
// ---------------------------------------------------------------------------
namespace {
constexpr int GSTAGES = 2;
constexpr uint32_t ROWB  = 80;                 // 32 fp16 data + 16B pad
constexpr uint32_t COMP  = 128 * ROWB;         // 10240 B per component tile
constexpr uint32_t STAGE = 2 * COMP;           // A, B = 20480 B
constexpr uint32_t GSMEM = GSTAGES * STAGE + 512;  // ~41.5 KB -> 4 CTAs/SM smem-wise
}

template <int MODE>
__global__ void __launch_bounds__(256, 4)
mgemm_kernel(const __half* __restrict__ A, const __half* __restrict__ Bw,
             const float* __restrict__ bias, float* __restrict__ C,
             __half* __restrict__ Ch,
             const float* __restrict__ bias2, const float* __restrict__ bias3,
             __half* __restrict__ Ch2, __half* __restrict__ Ch3,
             int Nn, int Kk) {
    extern __shared__ char smem[];
    uint32_t sb = smem_u32(smem);
    const int tid  = threadIdx.x;
    const int lane = tid & 31, wid = tid >> 5;
    const int bm = blockIdx.y * 128;
    const int bn = blockIdx.x * 128;
    const int wm = (wid & 3) * 32;
    const int wn = (wid >> 2) * 64;

    // qkv select (MODE 4): col block 0..7 -> q, 8..15 -> k, 16..23 -> v
    int sel = 0;
    const float* biasp = bias;
    __half* dsth = Ch;
    if (MODE == 4) {
        sel = bn >> 10;
        if (sel == 1) { biasp = bias2; dsth = Ch2; }
        else if (sel == 2) { biasp = bias3; dsth = Ch3; }
    }
    const int bncol = (MODE == 4) ? (bn & 1023) : bn;
    const int NnO   = (MODE == 4) ? 1024 : Nn;

    float* sbias = reinterpret_cast<float*>(smem + GSTAGES * STAGE);
    if (tid < 128) sbias[tid] = biasp[bncol + tid];

    const int NK = Kk >> 5;

    auto load_stage = [&](int kt, int st) {
        uint32_t sdst = sb + (uint32_t)st * STAGE;
        int k0 = kt * 32;
#pragma unroll
        for (int comp = 0; comp < 2; ++comp) {
            const __half* g = (comp == 0) ? A : Bw;
            int rbase = (comp == 0) ? bm : bn;
#pragma unroll
            for (int t2 = 0; t2 < 2; ++t2) {
                int c   = tid + t2 * 256;
                int row = c >> 2, cc = c & 3;
                const __half* src = g + (size_t)(rbase + row) * Kk + k0 + cc * 8;
                uint32_t dst = sdst + (uint32_t)comp * COMP + (uint32_t)row * ROWB + cc * 16;
                CP_ASYNC16(dst, src);
            }
        }
    };

    load_stage(0, 0); CP_COMMIT();

    // single fp16 accumulator set: 2x8x2 u32 = 32 regs
    uint32_t acc[2][8][2] = {};

    uint32_t a_off[2], b_off[4];
#pragma unroll
    for (int i = 0; i < 2; ++i)
        a_off[i] = (uint32_t)((wm + i * 16 + (lane & 15)) * ROWB + ((lane >> 4) * 8) * 2);
#pragma unroll
    for (int p = 0; p < 4; ++p)
        b_off[p] = (uint32_t)((wn + p * 16 + ((lane >> 4) & 1) * 8 + (lane & 7)) * ROWB +
                              (((lane >> 3) & 1) * 8) * 2);

    int st = 0;
    for (int kt = 0; kt < NK; ++kt) {
        bool more = (kt + 1 < NK);
        if (more) { load_stage(kt + 1, st ^ 1); CP_COMMIT(); }
        if (more) CP_WAIT1(); else CP_WAIT0();
        __syncthreads();

        uint32_t sA = sb + (uint32_t)st * STAGE;
        uint32_t sB = sA + COMP;

#pragma unroll
        for (int kk = 0; kk < 2; ++kk) {
            uint32_t kb = (uint32_t)kk * 32;
            uint32_t ar[2][4];
#pragma unroll
            for (int i = 0; i < 2; ++i) ldmx4(ar[i], sA + a_off[i] + kb);
#pragma unroll
            for (int p = 0; p < 4; ++p) {
                uint32_t br[4];
                ldmx4(br, sB + b_off[p] + kb);
#pragma unroll
                for (int i = 0; i < 2; ++i) {
                    mma16816h(acc[i][p * 2 + 0], ar[i], &br[0]);
                    mma16816h(acc[i][p * 2 + 1], ar[i], &br[2]);
                }
            }
        }
        __syncthreads();   // all warps done reading buffer st before it is reloaded
        st ^= 1;
    }

    // epilogue: v = float(acc) + bias
    const int r_ = lane >> 2;
    const int c_ = (lane & 3) * 2;
    const bool do_elu = (MODE == 3) || (MODE == 4 && sel < 2);
#pragma unroll
    for (int i = 0; i < 2; ++i) {
#pragma unroll
        for (int j = 0; j < 8; ++j) {
            int lrow = wm + i * 16 + r_;
            int lcol = wn + j * 8 + c_;
            size_t row0 = (size_t)(bm + lrow);
            int col = bncol + lcol;
            float b0 = sbias[lcol], b1 = sbias[lcol + 1];
            float2 a0 = __half22float2(*reinterpret_cast<const __half2*>(&acc[i][j][0]));
            float2 a1 = __half22float2(*reinterpret_cast<const __half2*>(&acc[i][j][1]));
            float v[4];
            v[0] = a0.x + b0; v[1] = a0.y + b1;
            v[2] = a1.x + b0; v[3] = a1.y + b1;
            if (do_elu) {
#pragma unroll
                for (int s = 0; s < 4; ++s) v[s] = (v[s] > 0.f) ? (v[s] + 1.f) : expf(v[s]);
            } else if (MODE == 1) {
#pragma unroll
                for (int s = 0; s < 4; ++s) v[s] = fmaxf(v[s], 0.f);
            }
            if (MODE == 2) {
                float* c0 = C + row0 * Nn + col;
                float* c1 = C + (row0 + 8) * Nn + col;
                float2 e0 = *reinterpret_cast<const float2*>(c0);
                float2 e1 = *reinterpret_cast<const float2*>(c1);
                v[0] += e0.x; v[1] += e0.y; v[2] += e1.x; v[3] += e1.y;
                *reinterpret_cast<float2*>(c0) = make_float2(v[0], v[1]);
                *reinterpret_cast<float2*>(c1) = make_float2(v[2], v[3]);
            } else {
                *reinterpret_cast<__half2*>(dsth + row0 * NnO + col)       = __floats2half2_rn(v[0], v[1]);
                *reinterpret_cast<__half2*>(dsth + (row0 + 8) * NnO + col) = __floats2half2_rn(v[2], v[3]);
            }
        }
    }
}

// ---------------------------------------------------------------------------
// Batched weight transpose: all 24 matrices in ONE launch.
// ---------------------------------------------------------------------------
__global__ void transpose_all_kernel(const float* __restrict__ Wq, const float* __restrict__ Wk,
                                     const float* __restrict__ Wv, const float* __restrict__ Wo,
                                     const float* __restrict__ W1, const float* __restrict__ W2,
                                     __half* __restrict__ wh) {
    int idx = blockIdx.x;
    int layer = idx / 12288;
    int rem   = idx % 12288;
    const float* in; __half* out; int R, C, tile;
    size_t wb = (size_t)layer * WBLK;
    if (rem < 4096) {
        int mat = rem >> 10; tile = rem & 1023;
        R = D; C = D;
        in  = (mat == 0 ? Wq : mat == 1 ? Wk : mat == 2 ? Wv : Wo) + (size_t)layer * DD;
        out = wh + wb + (size_t)mat * DD;
    } else if (rem < 8192) {
        tile = rem - 4096; R = D; C = F;
        in  = W1 + (size_t)layer * DF;
        out = wh + wb + 4 * DD;
    } else {
        tile = rem - 8192; R = F; C = D;
        in  = W2 + (size_t)layer * DF;
        out = wh + wb + 4 * DD + DF;
    }
    int gx = C >> 5;
    int bx = tile % gx, by = tile / gx;
    __shared__ float t[32][33];
    int x  = bx * 32 + threadIdx.x;
    int y0 = by * 32;
#pragma unroll
    for (int j = 0; j < 32; j += 8)
        t[threadIdx.y + j][threadIdx.x] = in[(size_t)(y0 + threadIdx.y + j) * C + x];
    __syncthreads();
    int ox  = y0 + threadIdx.x;
    int oy0 = bx * 32;
#pragma unroll
    for (int j = 0; j < 32; j += 8)
        out[(size_t)(oy0 + threadIdx.y + j) * R + ox] = __float2half(t[threadIdx.x][threadIdx.y + j]);
}

// ---------------------------------------------------------------------------
// Fused PE + embed: compute each sinusoid ONCE, apply to all 8 batch rows.
// ---------------------------------------------------------------------------
__global__ void embed_kernel(const float4* __restrict__ xin, float4* __restrict__ out) {
    int i = blockIdx.x * blockDim.x + threadIdx.x;
    int e0 = i * 4;
    int d0 = e0 & (D - 1);
    int t  = e0 >> 10;
    float pos = (float)(t + 1);
    const float nlf = -9.21034037197618f / 511.0f;
    float pe[4];
#pragma unroll
    for (int j = 0; j < 4; ++j) {
        int d = d0 + j;
        if (d < 512) pe[j] = sinf(pos * expf(nlf * (float)d));
        else         pe[j] = cosf(pos * expf(nlf * (float)(d - 512)));
    }
    const int TD4 = T * D / 4;
#pragma unroll
    for (int b = 0; b < B; ++b) {
        float4 xv = xin[(size_t)b * TD4 + i];
        out[(size_t)b * TD4 + i] = make_float4(32.0f * xv.x + pe[0], 32.0f * xv.y + pe[1],
                                               32.0f * xv.z + pe[2], 32.0f * xv.w + pe[3]);
    }
}

// ---------------------------------------------------------------------------
// LayerNorm. OUT16=1: write fp16; else fp32
// ---------------------------------------------------------------------------
template <int OUT16>
__global__ void ln_kernel(const float* __restrict__ x, const float* __restrict__ sc,
                          const float* __restrict__ bi, float* __restrict__ outf,
                          __half* __restrict__ oh) {
    int row = blockIdx.x, tid = threadIdx.x;
    const float4* xr = reinterpret_cast<const float4*>(x + (size_t)row * D);
    float4 v = xr[tid];
    float s = v.x + v.y + v.z + v.w;
    float q = v.x * v.x + v.y * v.y + v.z * v.z + v.w * v.w;
#pragma unroll
    for (int o = 16; o > 0; o >>= 1) {
        s += __shfl_xor_sync(0xffffffffu, s, o);
        q += __shfl_xor_sync(0xffffffffu, q, o);
    }
    __shared__ float ss[8], sq[8];
    if ((tid & 31) == 0) { ss[tid >> 5] = s; sq[tid >> 5] = q; }
    __syncthreads();
    s = 0.f; q = 0.f;
#pragma unroll
    for (int w = 0; w < 8; ++w) { s += ss[w]; q += sq[w]; }
    float mu  = s * (1.0f / D);
    float var = q * (1.0f / D) - mu * mu;
    float rs  = rsqrtf(var + 1e-5f);
    float4 s4 = reinterpret_cast<const float4*>(sc)[tid];
    float4 b4 = reinterpret_cast<const float4*>(bi)[tid];
    float o0 = (v.x - mu) * rs * s4.x + b4.x;
    float o1 = (v.y - mu) * rs * s4.y + b4.y;
    float o2 = (v.z - mu) * rs * s4.z + b4.z;
    float o3 = (v.w - mu) * rs * s4.w + b4.w;
    if (OUT16) {
        __half2* ohp = reinterpret_cast<__half2*>(oh + (size_t)row * D);
        ohp[tid * 2]     = __floats2half2_rn(o0, o1);
        ohp[tid * 2 + 1] = __floats2half2_rn(o2, o3);
    } else {
        reinterpret_cast<float4*>(outf + (size_t)row * D)[tid] = make_float4(o0, o1, o2, o3);
    }
}

// ---------------------------------------------------------------------------
// kv partial over T-slice
// ---------------------------------------------------------------------------
__global__ void kv_kernel(const __half* __restrict__ kp, const __half* __restrict__ vv,
                          float* __restrict__ kvp, float* __restrict__ ksp) {
    int g = blockIdx.x;
    int bh = g >> 3, slice = g & 7;
    int b = bh / H, h = bh % H;
    __shared__ float ks[32][64];
    __shared__ float vs[32][64];
    int tid = threadIdx.x;
    int tm = (tid / 16) * 4;
    int td = (tid % 16) * 4;
    float acc[4][4] = {};
    float ksacc = 0.f;
    int lr = tid / 8;
    int lc = (tid % 8) * 8;
    size_t base = ((size_t)b * T * H + h) * DK;
    int tbeg = slice * (T / NSPL), tend = tbeg + (T / NSPL);

    for (int t0 = tbeg; t0 < tend; t0 += 32) {
        uint4 ku = *reinterpret_cast<const uint4*>(kp + base + (size_t)(t0 + lr) * (H * DK) + lc);
        uint4 vu = *reinterpret_cast<const uint4*>(vv + base + (size_t)(t0 + lr) * (H * DK) + lc);
        h8_to_f(ku, &ks[lr][lc]);
        h8_to_f(vu, &vs[lr][lc]);
        __syncthreads();
#pragma unroll 8
        for (int t = 0; t < 32; ++t) {
            float4 vm = *reinterpret_cast<const float4*>(&vs[t][tm]);
            float4 kd = *reinterpret_cast<const float4*>(&ks[t][td]);
            float vr[4] = {vm.x, vm.y, vm.z, vm.w};
            float kr[4] = {kd.x, kd.y, kd.z, kd.w};
#pragma unroll
            for (int i = 0; i < 4; ++i)
#pragma unroll
                for (int j = 0; j < 4; ++j)
                    acc[i][j] = fmaf(vr[i], kr[j], acc[i][j]);
        }
        if (tid < 64) {
#pragma unroll 8
            for (int t = 0; t < 32; ++t) ksacc += ks[t][tid];
        }
        __syncthreads();
    }
    float* kvb = kvp + (size_t)g * DK * DK;
#pragma unroll
    for (int i = 0; i < 4; ++i)
        *reinterpret_cast<float4*>(&kvb[(size_t)(tm + i) * DK + td]) =
            make_float4(acc[i][0], acc[i][1], acc[i][2], acc[i][3]);
    if (tid < 64) ksp[g * DK + tid] = ksacc;
}

__global__ void kvreduce_kernel(const float* __restrict__ kvp, const float* __restrict__ ksp,
                                float* __restrict__ kv, float* __restrict__ ksum) {
    int i = blockIdx.x * 256 + threadIdx.x;
    int bh = i / (DK * DK);
    int e  = i % (DK * DK);
    float s = 0.f;
#pragma unroll
    for (int s8 = 0; s8 < NSPL; ++s8)
        s += kvp[((size_t)(bh * NSPL + s8)) * (DK * DK) + e];
    kv[i] = s;
    if (i < B * H * DK) {
        int bh2 = i / DK, d = i % DK;
        float t = 0.f;
#pragma unroll
        for (int s8 = 0; s8 < NSPL; ++s8)
            t += ksp[(bh2 * NSPL + s8) * DK + d];
        ksum[i] = t;
    }
}

// ---------------------------------------------------------------------------
// attn out
// ---------------------------------------------------------------------------
__global__ void attnout_kernel(const __half* __restrict__ qp, const float* __restrict__ kv,
                               const float* __restrict__ ksum, __half* __restrict__ oh) {
    constexpr int NCH = T / 64;
    int id = blockIdx.x;
    int chunk = id % NCH;
    int h = (id / NCH) % H;
    int b = id / (NCH * H);
    __shared__ float kvs[64 * 64];
    __shared__ float qs[64][64];
    __shared__ float kss[64];
    int tid = threadIdx.x;
    const float* kvg = kv + (size_t)(b * H + h) * (DK * DK);
#pragma unroll
    for (int it = 0; it < 8; ++it) {
        int g  = tid + it * 128;
        int m  = g >> 4;
        int d0 = (g & 15) * 4;
        float4 val = reinterpret_cast<const float4*>(kvg)[g];
        kvs[(d0 + 0) * 64 + m] = val.x;
        kvs[(d0 + 1) * 64 + m] = val.y;
        kvs[(d0 + 2) * 64 + m] = val.z;
        kvs[(d0 + 3) * 64 + m] = val.w;
    }
    if (tid < 64) kss[tid] = ksum[(b * H + h) * DK + tid];
    int t0 = chunk * 64;
    size_t qbase = (((size_t)b * T + t0) * H + h) * DK;
    {
        int r = tid >> 1;
        int c = (tid & 1) * 32;
        const __half* qg = qp + qbase + (size_t)r * (H * DK) + c;
#pragma unroll
        for (int j = 0; j < 4; ++j) {
            uint4 u = *reinterpret_cast<const uint4*>(qg + j * 8);
            h8_to_f(u, &qs[r][c + j * 8]);
        }
    }
    __syncthreads();

    int mm = tid & 63;
    int hf = tid >> 6;
    for (int r = hf; r < 64; r += 2) {
        float o = 0.f, den = 0.f;
#pragma unroll
        for (int d = 0; d < 64; d += 4) {
            float4 q4 = *reinterpret_cast<const float4*>(&qs[r][d]);
            float4 k4 = *reinterpret_cast<const float4*>(&kss[d]);
            den += q4.x * k4.x + q4.y * k4.y + q4.z * k4.z + q4.w * k4.w;
            o = fmaf(q4.x, kvs[(d + 0) * 64 + mm], o);
            o = fmaf(q4.y, kvs[(d + 1) * 64 + mm], o);
            o = fmaf(q4.z, kvs[(d + 2) * 64 + mm], o);
            o = fmaf(q4.w, kvs[(d + 3) * 64 + mm], o);
        }
        oh[qbase + (size_t)r * (H * DK) + mm] = __float2half(o / (den + 1e-6f));
    }
}

// ---------------------------------------------------------------------------
// Host orchestration
// ---------------------------------------------------------------------------
static inline void mgemm(int mode, const __half* A, const __half* Bw,
                         const float* bias, float* C, __half* Ch, int n, int k) {
    dim3 g(n / 128, M / 128), blk(256);
    switch (mode) {
        case 0: mgemm_kernel<0><<<g, blk, GSMEM>>>(A, Bw, bias, C, Ch, nullptr, nullptr, nullptr, nullptr, n, k); break;
        case 1: mgemm_kernel<1><<<g, blk, GSMEM>>>(A, Bw, bias, C, Ch, nullptr, nullptr, nullptr, nullptr, n, k); break;
        case 2: mgemm_kernel<2><<<g, blk, GSMEM>>>(A, Bw, bias, C, Ch, nullptr, nullptr, nullptr, nullptr, n, k); break;
        case 3: mgemm_kernel<3><<<g, blk, GSMEM>>>(A, Bw, bias, C, Ch, nullptr, nullptr, nullptr, nullptr, n, k); break;
    }
}

extern "C" void kernel_launch(void* const* d_in, const int* in_sizes, int n_in,
                              void* d_out, int out_size) {
    const float* x_in  = (const float*)d_in[0];
    const float* Wq    = (const float*)d_in[1];
    const float* bq    = (const float*)d_in[2];
    const float* Wk    = (const float*)d_in[3];
    const float* bk    = (const float*)d_in[4];
    const float* Wv    = (const float*)d_in[5];
    const float* bv    = (const float*)d_in[6];
    const float* Wo    = (const float*)d_in[7];
    const float* bo    = (const float*)d_in[8];
    const float* W1    = (const float*)d_in[9];
    const float* b1    = (const float*)d_in[10];
    const float* W2    = (const float*)d_in[11];
    const float* b2    = (const float*)d_in[12];
    const float* ln1_s = (const float*)d_in[13];
    const float* ln1_b = (const float*)d_in[14];
    const float* ln2_s = (const float*)d_in[15];
    const float* ln2_b = (const float*)d_in[16];
    const float* lnf_s = (const float*)d_in[17];
    const float* lnf_b = (const float*)d_in[18];

    cudaFuncSetAttribute(mgemm_kernel<0>, cudaFuncAttributeMaxDynamicSharedMemorySize, GSMEM);
    cudaFuncSetAttribute(mgemm_kernel<1>, cudaFuncAttributeMaxDynamicSharedMemorySize, GSMEM);
    cudaFuncSetAttribute(mgemm_kernel<2>, cudaFuncAttributeMaxDynamicSharedMemorySize, GSMEM);
    cudaFuncSetAttribute(mgemm_kernel<3>, cudaFuncAttributeMaxDynamicSharedMemorySize, GSMEM);
    cudaFuncSetAttribute(mgemm_kernel<4>, cudaFuncAttributeMaxDynamicSharedMemorySize, GSMEM);

    float* x = (float*)d_out;
    __half *hh, *ohp, *fh, *wh, *q, *k, *v;
    float *kvpp, *kspp, *kvb, *ksb;
    cudaGetSymbolAddress((void**)&hh,   g_hh);
    cudaGetSymbolAddress((void**)&ohp,  g_oh);
    cudaGetSymbolAddress((void**)&fh,   g_fh);
    cudaGetSymbolAddress((void**)&q,    g_q);
    cudaGetSymbolAddress((void**)&k,    g_k);
    cudaGetSymbolAddress((void**)&v,    g_v);
    cudaGetSymbolAddress((void**)&kvpp, g_kvp);
    cudaGetSymbolAddress((void**)&kspp, g_ksp);
    cudaGetSymbolAddress((void**)&kvb,  g_kv);
    cudaGetSymbolAddress((void**)&ksb,  g_ksum);
    cudaGetSymbolAddress((void**)&wh,   g_wh);

    // Launch order keeps the qkv GEMM in the profiled slot:
    embed_kernel<<<(T * D / 4) / 256, 256>>>((const float4*)x_in, (float4*)x);
    ln_kernel<1><<<M, 256>>>(x, ln1_s, ln1_b, nullptr, hh);          // layer 0 ln1
    transpose_all_kernel<<<NL * 12288, dim3(32, 8)>>>(Wq, Wk, Wv, Wo, W1, W2, wh);

    for (int l = 0; l < NL; ++l) {
        size_t wb  = (size_t)l * WBLK;
        size_t bo_ = (size_t)l * D;
        size_t b1o = (size_t)l * F;
        const __half *wqkv = wh + wb;               // q,k,v weights contiguous [3072][1024]
        const __half *wo_  = wh + wb + 3 * DD;
        const __half *w1   = wh + wb + 4 * DD;
        const __half *w2   = wh + wb + 4 * DD + DF;

        // --- attention block ---
        if (l > 0)
            ln_kernel<1><<<M, 256>>>(x, ln1_s + bo_, ln1_b + bo_, nullptr, hh);
        // fused q/k/v: one launch, N = 3072
        mgemm_kernel<4><<<dim3(3072 / 128, M / 128), 256, GSMEM>>>(
            hh, wqkv, bq + bo_, nullptr, q, bk + bo_, bv + bo_, k, v, 3072, D);
        kv_kernel<<<B * H * NSPL, 256>>>(k, v, kvpp, kspp);
        kvreduce_kernel<<<(B * H * DK * DK) / 256, 256>>>(kvpp, kspp, kvb, ksb);
        attnout_kernel<<<B * H * (T / 64), 128>>>(q, kvb, ksb, ohp);
        mgemm(2, ohp, wo_, bo + bo_, x, nullptr, D, D);   // x += attn@Wo (fp32)

        // --- ffn block ---
        ln_kernel<1><<<M, 256>>>(x, ln2_s + bo_, ln2_b + bo_, nullptr, hh);
        mgemm(1, hh, w1, b1 + b1o, nullptr, fh, F, D);    // relu -> fp16
        mgemm(2, fh, w2, b2 + bo_, x, nullptr, D, F);     // x += ffn@W2 (fp32)
    }

    ln_kernel<0><<<M, 256>>>(x, lnf_s, lnf_b, x, nullptr);
}

// round 17
// speedup vs baseline: 1.1378x; 1.1378x over previous
#include <cuda_runtime.h>
#include <cuda_fp16.h>
#include <cstdint>

// ---------------------------------------------------------------------------
// Problem constants
// ---------------------------------------------------------------------------
namespace {
constexpr int B  = 8;
constexpr int T  = 2048;
constexpr int D  = 1024;
constexpr int H  = 16;
constexpr int NL = 4;
constexpr int DK = 64;           // D / H
constexpr int M  = B * T;        // 16384 rows
constexpr int F  = 4 * D;        // 4096 ffn hidden
constexpr int NSPL = 8;          // kv T-splits
constexpr size_t DD   = (size_t)D * D;
constexpr size_t DF   = (size_t)D * F;
constexpr size_t WBLK = 4 * DD + 2 * DF;   // weight block per layer
}

// ---------------------------------------------------------------------------
// Scratch (static device memory — no allocations allowed)
// ---------------------------------------------------------------------------
__device__ __half g_hh[(size_t)M * D];     // LN out (fp16)
__device__ __half g_oh[(size_t)M * D];     // attn out (fp16)
__device__ __half g_fh[(size_t)M * F];     // relu(ffn) (fp16)
__device__ __half g_q[(size_t)M * D];
__device__ __half g_k[(size_t)M * D];
__device__ __half g_v[(size_t)M * D];
__device__ float g_kvp [B * H * NSPL * DK * DK];   // kv partials
__device__ float g_ksp [B * H * NSPL * DK];        // ksum partials
__device__ float g_kv  [B * H * DK * DK];
__device__ float g_ksum[B * H * DK];
__device__ __half g_wh[(size_t)NL * WBLK]; // transposed weights [N][K] fp16

// ---------------------------------------------------------------------------
// Helpers
// ---------------------------------------------------------------------------
__device__ __forceinline__ uint32_t smem_u32(const void* p) {
    uint32_t a;
    asm("{ .reg .u64 t; cvta.to.shared.u64 t, %1; cvt.u32.u64 %0, t; }" : "=r"(a) : "l"(p));
    return a;
}
__device__ __forceinline__ void ldmx4(uint32_t* r, uint32_t addr) {
    asm volatile("ldmatrix.sync.aligned.m8n8.x4.shared.b16 {%0,%1,%2,%3}, [%4];"
                 : "=r"(r[0]), "=r"(r[1]), "=r"(r[2]), "=r"(r[3]) : "r"(addr));
}
// fp16-accumulate MMA: D(f16x2 x2) += A x B
__device__ __forceinline__ void mma16816h(uint32_t* d, const uint32_t* a, const uint32_t* b) {
    asm volatile(
        "mma.sync.aligned.m16n8k16.row.col.f16.f16.f16.f16 "
        "{%0,%1}, {%2,%3,%4,%5}, {%6,%7}, {%0,%1};"
        : "+r"(d[0]), "+r"(d[1])
        : "r"(a[0]), "r"(a[1]), "r"(a[2]), "r"(a[3]), "r"(b[0]), "r"(b[1]));
}
#define CP_ASYNC16(dst, src) \
    asm volatile("cp.async.cg.shared.global [%0], [%1], 16;" :: "r"(dst), "l"(src))
#define CP_COMMIT() asm volatile("cp.async.commit_group;" ::: "memory")
#define CP_WAIT1()  asm volatile("cp.async.wait_group 1;" ::: "memory")

__device__ __forceinline__ void h8_to_f(const uint4& u, float* f) {
    const __half2* h2 = reinterpret_cast<const __half2*>(&u);
#pragma unroll
    for (int i = 0; i < 4; ++i) {
        float2 t = __half22float2(h2[i]);
        f[i * 2] = t.x; f[i * 2 + 1] = t.y;
    }
}

// ---------------------------------------------------------------------------
// mma.sync fp16 GEMM (fp16 accumulate, 3 CTAs/SM — PROVEN R14 core,
// with corrected pipeline wait: CP_WAIT1 guarantees tile kt landed):
//   out = op( A[M,K] @ B[N,K]^T + bias )
// CTA 128x128, BK=32, 3-stage cp.async pipeline, 8 warps (4x2)
// MODE 0: plain -> fp16   1: relu -> fp16   2: residual add -> fp32
// MODE 3: elu+1 -> fp16   4: fused qkv (col block selects q/k/v + activation)
// ---------------------------------------------------------------------------
namespace {
constexpr int GSTAGES = 3;
constexpr uint32_t ROWB  = 80;                 // 32 fp16 data + 16B pad
constexpr uint32_t COMP  = 128 * ROWB;         // 10240 B per component tile
constexpr uint32_t STAGE = 2 * COMP;           // A, B = 20480 B
constexpr uint32_t GSMEM = GSTAGES * STAGE + 512;  // ~62 KB -> 3 CTAs/SM
}

template <int MODE>
__global__ void __launch_bounds__(256, 3)
mgemm_kernel(const __half* __restrict__ A, const __half* __restrict__ Bw,
             const float* __restrict__ bias, float* __restrict__ C,
             __half* __restrict__ Ch,
             const float* __restrict__ bias2, const float* __restrict__ bias3,
             __half* __restrict__ Ch2, __half* __restrict__ Ch3,
             int Nn, int Kk) {
    extern __shared__ char smem[];
    uint32_t sb = smem_u32(smem);
    const int tid  = threadIdx.x;
    const int lane = tid & 31, wid = tid >> 5;
    const int bm = blockIdx.y * 128;
    const int bn = blockIdx.x * 128;
    const int wm = (wid & 3) * 32;
    const int wn = (wid >> 2) * 64;

    // qkv select (MODE 4): col block 0..7 -> q, 8..15 -> k, 16..23 -> v
    int sel = 0;
    const float* biasp = bias;
    __half* dsth = Ch;
    if (MODE == 4) {
        sel = bn >> 10;
        if (sel == 1) { biasp = bias2; dsth = Ch2; }
        else if (sel == 2) { biasp = bias3; dsth = Ch3; }
    }
    const int bncol = (MODE == 4) ? (bn & 1023) : bn;
    const int NnO   = (MODE == 4) ? 1024 : Nn;

    float* sbias = reinterpret_cast<float*>(smem + GSTAGES * STAGE);
    if (tid < 128) sbias[tid] = biasp[bncol + tid];

    const int NK = Kk >> 5;

    auto load_stage = [&](int kt, int st) {
        uint32_t sdst = sb + (uint32_t)st * STAGE;
        int k0 = kt * 32;
#pragma unroll
        for (int comp = 0; comp < 2; ++comp) {
            const __half* g = (comp == 0) ? A : Bw;
            int rbase = (comp == 0) ? bm : bn;
#pragma unroll
            for (int t2 = 0; t2 < 2; ++t2) {
                int c   = tid + t2 * 256;
                int row = c >> 2, cc = c & 3;
                const __half* src = g + (size_t)(rbase + row) * Kk + k0 + cc * 8;
                uint32_t dst = sdst + (uint32_t)comp * COMP + (uint32_t)row * ROWB + cc * 16;
                CP_ASYNC16(dst, src);
            }
        }
    };

    load_stage(0, 0); CP_COMMIT();
    load_stage(1, 1); CP_COMMIT();

    // single fp16 accumulator set: 2x8x2 u32 = 32 regs
    uint32_t acc[2][8][2] = {};

    uint32_t a_off[2], b_off[4];
#pragma unroll
    for (int i = 0; i < 2; ++i)
        a_off[i] = (uint32_t)((wm + i * 16 + (lane & 15)) * ROWB + ((lane >> 4) * 8) * 2);
#pragma unroll
    for (int p = 0; p < 4; ++p)
        b_off[p] = (uint32_t)((wn + p * 16 + ((lane >> 4) & 1) * 8 + (lane & 7)) * ROWB +
                              (((lane >> 3) & 1) * 8) * 2);

    int st = 0;
    for (int kt = 0; kt < NK; ++kt) {
        // 2 groups in flight here ({kt, kt+1}); wait until <=1 pending
        // => tile kt guaranteed landed (R16 NaN root cause fix).
        CP_WAIT1();
        __syncthreads();
        {
            int ldk = kt + 2;
            if (ldk < NK) {
                int ls = st + 2; if (ls >= GSTAGES) ls -= GSTAGES;
                load_stage(ldk, ls);
            }
        }
        CP_COMMIT();

        uint32_t sA = sb + (uint32_t)st * STAGE;
        uint32_t sB = sA + COMP;

#pragma unroll
        for (int kk = 0; kk < 2; ++kk) {
            uint32_t kb = (uint32_t)kk * 32;
            uint32_t ar[2][4], br[4][4];
#pragma unroll
            for (int i = 0; i < 2; ++i) ldmx4(ar[i], sA + a_off[i] + kb);
#pragma unroll
            for (int p = 0; p < 4; ++p) ldmx4(br[p], sB + b_off[p] + kb);
#pragma unroll
            for (int i = 0; i < 2; ++i)
#pragma unroll
                for (int p = 0; p < 4; ++p)
#pragma unroll
                    for (int q2 = 0; q2 < 2; ++q2)
                        mma16816h(acc[i][p * 2 + q2], ar[i], &br[p][q2 * 2]);
        }
        if (++st == GSTAGES) st = 0;
    }

    // epilogue: v = float(acc) + bias
    const int r_ = lane >> 2;
    const int c_ = (lane & 3) * 2;
    const bool do_elu = (MODE == 3) || (MODE == 4 && sel < 2);
#pragma unroll
    for (int i = 0; i < 2; ++i) {
#pragma unroll
        for (int j = 0; j < 8; ++j) {
            int lrow = wm + i * 16 + r_;
            int lcol = wn + j * 8 + c_;
            size_t row0 = (size_t)(bm + lrow);
            int col = bncol + lcol;
            float b0 = sbias[lcol], b1 = sbias[lcol + 1];
            float2 a0 = __half22float2(*reinterpret_cast<const __half2*>(&acc[i][j][0]));
            float2 a1 = __half22float2(*reinterpret_cast<const __half2*>(&acc[i][j][1]));
            float v[4];
            v[0] = a0.x + b0; v[1] = a0.y + b1;
            v[2] = a1.x + b0; v[3] = a1.y + b1;
            if (do_elu) {
#pragma unroll
                for (int s = 0; s < 4; ++s) v[s] = (v[s] > 0.f) ? (v[s] + 1.f) : expf(v[s]);
            } else if (MODE == 1) {
#pragma unroll
                for (int s = 0; s < 4; ++s) v[s] = fmaxf(v[s], 0.f);
            }
            if (MODE == 2) {
                float* c0 = C + row0 * Nn + col;
                float* c1 = C + (row0 + 8) * Nn + col;
                float2 e0 = *reinterpret_cast<const float2*>(c0);
                float2 e1 = *reinterpret_cast<const float2*>(c1);
                v[0] += e0.x; v[1] += e0.y; v[2] += e1.x; v[3] += e1.y;
                *reinterpret_cast<float2*>(c0) = make_float2(v[0], v[1]);
                *reinterpret_cast<float2*>(c1) = make_float2(v[2], v[3]);
            } else {
                *reinterpret_cast<__half2*>(dsth + row0 * NnO + col)       = __floats2half2_rn(v[0], v[1]);
                *reinterpret_cast<__half2*>(dsth + (row0 + 8) * NnO + col) = __floats2half2_rn(v[2], v[3]);
            }
        }
    }
}

// ---------------------------------------------------------------------------
// Batched weight transpose: all 24 matrices in ONE launch.
// ---------------------------------------------------------------------------
__global__ void transpose_all_kernel(const float* __restrict__ Wq, const float* __restrict__ Wk,
                                     const float* __restrict__ Wv, const float* __restrict__ Wo,
                                     const float* __restrict__ W1, const float* __restrict__ W2,
                                     __half* __restrict__ wh) {
    int idx = blockIdx.x;
    int layer = idx / 12288;
    int rem   = idx % 12288;
    const float* in; __half* out; int R, C, tile;
    size_t wb = (size_t)layer * WBLK;
    if (rem < 4096) {
        int mat = rem >> 10; tile = rem & 1023;
        R = D; C = D;
        in  = (mat == 0 ? Wq : mat == 1 ? Wk : mat == 2 ? Wv : Wo) + (size_t)layer * DD;
        out = wh + wb + (size_t)mat * DD;
    } else if (rem < 8192) {
        tile = rem - 4096; R = D; C = F;
        in  = W1 + (size_t)layer * DF;
        out = wh + wb + 4 * DD;
    } else {
        tile = rem - 8192; R = F; C = D;
        in  = W2 + (size_t)layer * DF;
        out = wh + wb + 4 * DD + DF;
    }
    int gx = C >> 5;
    int bx = tile % gx, by = tile / gx;
    __shared__ float t[32][33];
    int x  = bx * 32 + threadIdx.x;
    int y0 = by * 32;
#pragma unroll
    for (int j = 0; j < 32; j += 8)
        t[threadIdx.y + j][threadIdx.x] = in[(size_t)(y0 + threadIdx.y + j) * C + x];
    __syncthreads();
    int ox  = y0 + threadIdx.x;
    int oy0 = bx * 32;
#pragma unroll
    for (int j = 0; j < 32; j += 8)
        out[(size_t)(oy0 + threadIdx.y + j) * R + ox] = __float2half(t[threadIdx.x][threadIdx.y + j]);
}

// ---------------------------------------------------------------------------
// Fused PE + embed: compute each sinusoid ONCE, apply to all 8 batch rows.
// ---------------------------------------------------------------------------
__global__ void embed_kernel(const float4* __restrict__ xin, float4* __restrict__ out) {
    int i = blockIdx.x * blockDim.x + threadIdx.x;
    int e0 = i * 4;
    int d0 = e0 & (D - 1);
    int t  = e0 >> 10;
    float pos = (float)(t + 1);
    const float nlf = -9.21034037197618f / 511.0f;
    float pe[4];
#pragma unroll
    for (int j = 0; j < 4; ++j) {
        int d = d0 + j;
        if (d < 512) pe[j] = sinf(pos * expf(nlf * (float)d));
        else         pe[j] = cosf(pos * expf(nlf * (float)(d - 512)));
    }
    const int TD4 = T * D / 4;
#pragma unroll
    for (int b = 0; b < B; ++b) {
        float4 xv = xin[(size_t)b * TD4 + i];
        out[(size_t)b * TD4 + i] = make_float4(32.0f * xv.x + pe[0], 32.0f * xv.y + pe[1],
                                               32.0f * xv.z + pe[2], 32.0f * xv.w + pe[3]);
    }
}

// ---------------------------------------------------------------------------
// LayerNorm v2: warp-per-row, shuffle-only reduction, NO block barriers.
// block 256 = 8 warps -> 8 rows per block; grid = M/8.
// OUT16=1: write fp16; else fp32
// ---------------------------------------------------------------------------
template <int OUT16>
__global__ void __launch_bounds__(256)
ln_kernel(const float* __restrict__ x, const float* __restrict__ sc,
          const float* __restrict__ bi, float* __restrict__ outf,
          __half* __restrict__ oh) {
    const int w = threadIdx.x >> 5, lane = threadIdx.x & 31;
    const size_t row = (size_t)blockIdx.x * 8 + w;
    const float4* xr = reinterpret_cast<const float4*>(x + row * D);
    const float4* sc4 = reinterpret_cast<const float4*>(sc);
    const float4* bi4 = reinterpret_cast<const float4*>(bi);

    float4 v[8];
    float s = 0.f, q = 0.f;
#pragma unroll
    for (int j = 0; j < 8; ++j) {
        v[j] = xr[j * 32 + lane];
        s += v[j].x + v[j].y + v[j].z + v[j].w;
        q += v[j].x * v[j].x + v[j].y * v[j].y + v[j].z * v[j].z + v[j].w * v[j].w;
    }
#pragma unroll
    for (int o = 16; o > 0; o >>= 1) {
        s += __shfl_xor_sync(0xffffffffu, s, o);
        q += __shfl_xor_sync(0xffffffffu, q, o);
    }
    float mu  = s * (1.0f / D);
    float var = q * (1.0f / D) - mu * mu;
    float rs  = rsqrtf(var + 1e-5f);

#pragma unroll
    for (int j = 0; j < 8; ++j) {
        int c4 = j * 32 + lane;
        float4 s4 = sc4[c4];
        float4 b4 = bi4[c4];
        float o0 = (v[j].x - mu) * rs * s4.x + b4.x;
        float o1 = (v[j].y - mu) * rs * s4.y + b4.y;
        float o2 = (v[j].z - mu) * rs * s4.z + b4.z;
        float o3 = (v[j].w - mu) * rs * s4.w + b4.w;
        if (OUT16) {
            __half2* op = reinterpret_cast<__half2*>(oh + row * D + (size_t)c4 * 4);
            op[0] = __floats2half2_rn(o0, o1);
            op[1] = __floats2half2_rn(o2, o3);
        } else {
            reinterpret_cast<float4*>(outf + row * D)[c4] = make_float4(o0, o1, o2, o3);
        }
    }
}

// ---------------------------------------------------------------------------
// kv partial over T-slice
// ---------------------------------------------------------------------------
__global__ void kv_kernel(const __half* __restrict__ kp, const __half* __restrict__ vv,
                          float* __restrict__ kvp, float* __restrict__ ksp) {
    int g = blockIdx.x;
    int bh = g >> 3, slice = g & 7;
    int b = bh / H, h = bh % H;
    __shared__ float ks[32][64];
    __shared__ float vs[32][64];
    int tid = threadIdx.x;
    int tm = (tid / 16) * 4;
    int td = (tid % 16) * 4;
    float acc[4][4] = {};
    float ksacc = 0.f;
    int lr = tid / 8;
    int lc = (tid % 8) * 8;
    size_t base = ((size_t)b * T * H + h) * DK;
    int tbeg = slice * (T / NSPL), tend = tbeg + (T / NSPL);

    for (int t0 = tbeg; t0 < tend; t0 += 32) {
        uint4 ku = *reinterpret_cast<const uint4*>(kp + base + (size_t)(t0 + lr) * (H * DK) + lc);
        uint4 vu = *reinterpret_cast<const uint4*>(vv + base + (size_t)(t0 + lr) * (H * DK) + lc);
        h8_to_f(ku, &ks[lr][lc]);
        h8_to_f(vu, &vs[lr][lc]);
        __syncthreads();
#pragma unroll 8
        for (int t = 0; t < 32; ++t) {
            float4 vm = *reinterpret_cast<const float4*>(&vs[t][tm]);
            float4 kd = *reinterpret_cast<const float4*>(&ks[t][td]);
            float vr[4] = {vm.x, vm.y, vm.z, vm.w};
            float kr[4] = {kd.x, kd.y, kd.z, kd.w};
#pragma unroll
            for (int i = 0; i < 4; ++i)
#pragma unroll
                for (int j = 0; j < 4; ++j)
                    acc[i][j] = fmaf(vr[i], kr[j], acc[i][j]);
        }
        if (tid < 64) {
#pragma unroll 8
            for (int t = 0; t < 32; ++t) ksacc += ks[t][tid];
        }
        __syncthreads();
    }
    float* kvb = kvp + (size_t)g * DK * DK;
#pragma unroll
    for (int i = 0; i < 4; ++i)
        *reinterpret_cast<float4*>(&kvb[(size_t)(tm + i) * DK + td]) =
            make_float4(acc[i][0], acc[i][1], acc[i][2], acc[i][3]);
    if (tid < 64) ksp[g * DK + tid] = ksacc;
}

__global__ void kvreduce_kernel(const float* __restrict__ kvp, const float* __restrict__ ksp,
                                float* __restrict__ kv, float* __restrict__ ksum) {
    int i = blockIdx.x * 256 + threadIdx.x;
    int bh = i / (DK * DK);
    int e  = i % (DK * DK);
    float s = 0.f;
#pragma unroll
    for (int s8 = 0; s8 < NSPL; ++s8)
        s += kvp[((size_t)(bh * NSPL + s8)) * (DK * DK) + e];
    kv[i] = s;
    if (i < B * H * DK) {
        int bh2 = i / DK, d = i % DK;
        float t = 0.f;
#pragma unroll
        for (int s8 = 0; s8 < NSPL; ++s8)
            t += ksp[(bh2 * NSPL + s8) * DK + d];
        ksum[i] = t;
    }
}

// ---------------------------------------------------------------------------
// attn out
// ---------------------------------------------------------------------------
__global__ void attnout_kernel(const __half* __restrict__ qp, const float* __restrict__ kv,
                               const float* __restrict__ ksum, __half* __restrict__ oh) {
    constexpr int NCH = T / 64;
    int id = blockIdx.x;
    int chunk = id % NCH;
    int h = (id / NCH) % H;
    int b = id / (NCH * H);
    __shared__ float kvs[64 * 64];
    __shared__ float qs[64][64];
    __shared__ float kss[64];
    int tid = threadIdx.x;
    const float* kvg = kv + (size_t)(b * H + h) * (DK * DK);
#pragma unroll
    for (int it = 0; it < 8; ++it) {
        int g  = tid + it * 128;
        int m  = g >> 4;
        int d0 = (g & 15) * 4;
        float4 val = reinterpret_cast<const float4*>(kvg)[g];
        kvs[(d0 + 0) * 64 + m] = val.x;
        kvs[(d0 + 1) * 64 + m] = val.y;
        kvs[(d0 + 2) * 64 + m] = val.z;
        kvs[(d0 + 3) * 64 + m] = val.w;
    }
    if (tid < 64) kss[tid] = ksum[(b * H + h) * DK + tid];
    int t0 = chunk * 64;
    size_t qbase = (((size_t)b * T + t0) * H + h) * DK;
    {
        int r = tid >> 1;
        int c = (tid & 1) * 32;
        const __half* qg = qp + qbase + (size_t)r * (H * DK) + c;
#pragma unroll
        for (int j = 0; j < 4; ++j) {
            uint4 u = *reinterpret_cast<const uint4*>(qg + j * 8);
            h8_to_f(u, &qs[r][c + j * 8]);
        }
    }
    __syncthreads();

    int mm = tid & 63;
    int hf = tid >> 6;
    for (int r = hf; r < 64; r += 2) {
        float o = 0.f, den = 0.f;
#pragma unroll
        for (int d = 0; d < 64; d += 4) {
            float4 q4 = *reinterpret_cast<const float4*>(&qs[r][d]);
            float4 k4 = *reinterpret_cast<const float4*>(&kss[d]);
            den += q4.x * k4.x + q4.y * k4.y + q4.z * k4.z + q4.w * k4.w;
            o = fmaf(q4.x, kvs[(d + 0) * 64 + mm], o);
            o = fmaf(q4.y, kvs[(d + 1) * 64 + mm], o);
            o = fmaf(q4.z, kvs[(d + 2) * 64 + mm], o);
            o = fmaf(q4.w, kvs[(d + 3) * 64 + mm], o);
        }
        oh[qbase + (size_t)r * (H * DK) + mm] = __float2half(o / (den + 1e-6f));
    }
}

// ---------------------------------------------------------------------------
// Host orchestration
// ---------------------------------------------------------------------------
static inline void mgemm(int mode, const __half* A, const __half* Bw,
                         const float* bias, float* C, __half* Ch, int n, int k) {
    dim3 g(n / 128, M / 128), blk(256);
    switch (mode) {
        case 0: mgemm_kernel<0><<<g, blk, GSMEM>>>(A, Bw, bias, C, Ch, nullptr, nullptr, nullptr, nullptr, n, k); break;
        case 1: mgemm_kernel<1><<<g, blk, GSMEM>>>(A, Bw, bias, C, Ch, nullptr, nullptr, nullptr, nullptr, n, k); break;
        case 2: mgemm_kernel<2><<<g, blk, GSMEM>>>(A, Bw, bias, C, Ch, nullptr, nullptr, nullptr, nullptr, n, k); break;
        case 3: mgemm_kernel<3><<<g, blk, GSMEM>>>(A, Bw, bias, C, Ch, nullptr, nullptr, nullptr, nullptr, n, k); break;
    }
}

extern "C" void kernel_launch(void* const* d_in, const int* in_sizes, int n_in,
                              void* d_out, int out_size) {
    const float* x_in  = (const float*)d_in[0];
    const float* Wq    = (const float*)d_in[1];
    const float* bq    = (const float*)d_in[2];
    const float* Wk    = (const float*)d_in[3];
    const float* bk    = (const float*)d_in[4];
    const float* Wv    = (const float*)d_in[5];
    const float* bv    = (const float*)d_in[6];
    const float* Wo    = (const float*)d_in[7];
    const float* bo    = (const float*)d_in[8];
    const float* W1    = (const float*)d_in[9];
    const float* b1    = (const float*)d_in[10];
    const float* W2    = (const float*)d_in[11];
    const float* b2    = (const float*)d_in[12];
    const float* ln1_s = (const float*)d_in[13];
    const float* ln1_b = (const float*)d_in[14];
    const float* ln2_s = (const float*)d_in[15];
    const float* ln2_b = (const float*)d_in[16];
    const float* lnf_s = (const float*)d_in[17];
    const float* lnf_b = (const float*)d_in[18];

    cudaFuncSetAttribute(mgemm_kernel<0>, cudaFuncAttributeMaxDynamicSharedMemorySize, GSMEM);
    cudaFuncSetAttribute(mgemm_kernel<1>, cudaFuncAttributeMaxDynamicSharedMemorySize, GSMEM);
    cudaFuncSetAttribute(mgemm_kernel<2>, cudaFuncAttributeMaxDynamicSharedMemorySize, GSMEM);
    cudaFuncSetAttribute(mgemm_kernel<3>, cudaFuncAttributeMaxDynamicSharedMemorySize, GSMEM);
    cudaFuncSetAttribute(mgemm_kernel<4>, cudaFuncAttributeMaxDynamicSharedMemorySize, GSMEM);

    float* x = (float*)d_out;
    __half *hh, *ohp, *fh, *wh, *q, *k, *v;
    float *kvpp, *kspp, *kvb, *ksb;
    cudaGetSymbolAddress((void**)&hh,   g_hh);
    cudaGetSymbolAddress((void**)&ohp,  g_oh);
    cudaGetSymbolAddress((void**)&fh,   g_fh);
    cudaGetSymbolAddress((void**)&q,    g_q);
    cudaGetSymbolAddress((void**)&k,    g_k);
    cudaGetSymbolAddress((void**)&v,    g_v);
    cudaGetSymbolAddress((void**)&kvpp, g_kvp);
    cudaGetSymbolAddress((void**)&kspp, g_ksp);
    cudaGetSymbolAddress((void**)&kvb,  g_kv);
    cudaGetSymbolAddress((void**)&ksb,  g_ksum);
    cudaGetSymbolAddress((void**)&wh,   g_wh);

    // Launch order keeps the qkv GEMM in the profiled slot:
    embed_kernel<<<(T * D / 4) / 256, 256>>>((const float4*)x_in, (float4*)x);
    ln_kernel<1><<<M / 8, 256>>>(x, ln1_s, ln1_b, nullptr, hh);      // layer 0 ln1
    transpose_all_kernel<<<NL * 12288, dim3(32, 8)>>>(Wq, Wk, Wv, Wo, W1, W2, wh);

    for (int l = 0; l < NL; ++l) {
        size_t wb  = (size_t)l * WBLK;
        size_t bo_ = (size_t)l * D;
        size_t b1o = (size_t)l * F;
        const __half *wqkv = wh + wb;               // q,k,v weights contiguous [3072][1024]
        const __half *wo_  = wh + wb + 3 * DD;
        const __half *w1   = wh + wb + 4 * DD;
        const __half *w2   = wh + wb + 4 * DD + DF;

        // --- attention block ---
        if (l > 0)
            ln_kernel<1><<<M / 8, 256>>>(x, ln1_s + bo_, ln1_b + bo_, nullptr, hh);
        // fused q/k/v: one launch, N = 3072
        mgemm_kernel<4><<<dim3(3072 / 128, M / 128), 256, GSMEM>>>(
            hh, wqkv, bq + bo_, nullptr, q, bk + bo_, bv + bo_, k, v, 3072, D);
        kv_kernel<<<B * H * NSPL, 256>>>(k, v, kvpp, kspp);
        kvreduce_kernel<<<(B * H * DK * DK) / 256, 256>>>(kvpp, kspp, kvb, ksb);
        attnout_kernel<<<B * H * (T / 64), 128>>>(q, kvb, ksb, ohp);
        mgemm(2, ohp, wo_, bo + bo_, x, nullptr, D, D);   // x += attn@Wo (fp32)

        // --- ffn block ---
        ln_kernel<1><<<M / 8, 256>>>(x, ln2_s + bo_, ln2_b + bo_, nullptr, hh);
        mgemm(1, hh, w1, b1 + b1o, nullptr, fh, F, D);    // relu -> fp16
        mgemm(2, fh, w2, b2 + bo_, x, nullptr, D, F);     // x += ffn@W2 (fp32)
    }

    ln_kernel<0><<<M / 8, 256>>>(x, lnf_s, lnf_b, x, nullptr);
}